// round 12
// baseline (speedup 1.0000x reference)
#include <cuda_runtime.h>
#include <cuda_bf16.h>

#define NROW 8192
#define DIM  256
#define NB   64                  // 128-row blocks
#define NB2  32                  // 256-col super-blocks
#define NTILES2 1056             // sum over bi of (32 - bi/2)
#define GRID 132                 // 1056 = 8 * 132 (perfect balance)
#define CORRF (256.0f/255.0f)
#define KCONST (CORRF/128.0f)
#define HALF_BYTES 32768         // 128 rows x 128 bf16 (256B/row), swizzled
#define HALF_U4 (HALF_BYTES/16)  // 2048
#define NTHREADS 512
#define STAGE_BYTES 98304        // A-half 32KB + B-half 64KB

// ---------------- scratch ----------------
__device__ uint4  d_ebf4[NB * 2 * HALF_U4];
__device__ float4 d_rp[NROW];    // {V, 16*m, 1/V, label bits}

struct Acc {
    double pos_sum, neg_sum, reg_sum;
    unsigned long long pos_cnt, neg_cnt;
    unsigned done;
};
__device__ Acc d_acc;

__device__ __forceinline__ unsigned smem_u32(const void* p) {
    unsigned a;
    asm("{ .reg .u64 t; cvta.to.shared.u64 t, %1; cvt.u32.u64 %0, t; }" : "=r"(a) : "l"(p));
    return a;
}

#define LDSM_X4(r0, r1, r2, r3, a) \
    asm volatile("ldmatrix.sync.aligned.m8n8.x4.shared.b16 {%0,%1,%2,%3}, [%4];" \
        : "=r"(r0), "=r"(r1), "=r"(r2), "=r"(r3) : "r"(a))

#define MMA_BF16(d, a0, a1, a2, a3, b0, b1) \
    asm volatile("mma.sync.aligned.m16n8k16.row.col.f32.bf16.bf16.f32 " \
        "{%0,%1,%2,%3}, {%4,%5,%6,%7}, {%8,%9}, {%0,%1,%2,%3};" \
        : "+f"((d)[0]), "+f"((d)[1]), "+f"((d)[2]), "+f"((d)[3]) \
        : "r"(a0), "r"(a1), "r"(a2), "r"(a3), "r"(b0), "r"(b1))

#define CP16(sdst, gsrc) \
    asm volatile("cp.async.cg.shared.global [%0], [%1], 16;" :: "r"(sdst), "l"(gsrc))
#define CP_COMMIT()  asm volatile("cp.async.commit_group;" ::: "memory")
#define CP_WAIT(n)   asm volatile("cp.async.wait_group %0;" :: "n"(n) : "memory")

// ---------------- precompute: normalize, stats, bf16 swizzled store ----------------
__global__ void precompute_kernel(const float* __restrict__ x,
                                  const long long* __restrict__ lab) {
    int row = blockIdx.x;
    int t = threadIdx.x;                 // feature index, blockDim = 256
    float v = x[row * DIM + t];

    float ss = v * v;
    #pragma unroll
    for (int o = 16; o; o >>= 1) ss += __shfl_xor_sync(0xffffffffu, ss, o);
    __shared__ float red[8];
    if ((t & 31) == 0) red[t >> 5] = ss;
    __syncthreads();
    float tot = red[0] + red[1] + red[2] + red[3] + red[4] + red[5] + red[6] + red[7];

    float norm = sqrtf(tot);
    float e = v / norm;

    __shared__ __nv_bfloat16 sh_e[DIM];
    sh_e[t] = __float2bfloat16(e);

    float s1 = e, s2 = e * e;
    #pragma unroll
    for (int o = 16; o; o >>= 1) {
        s1 += __shfl_xor_sync(0xffffffffu, s1, o);
        s2 += __shfl_xor_sync(0xffffffffu, s2, o);
    }
    __shared__ float red1[8], red2[8];
    if ((t & 31) == 0) { red1[t >> 5] = s1; red2[t >> 5] = s2; }
    __syncthreads();

    if (t < 32) {
        int c = t;                       // global 16B chunk index 0..31
        int k0 = c * 8;
        unsigned w0 = (unsigned)__bfloat16_as_ushort(sh_e[k0 + 0]) | ((unsigned)__bfloat16_as_ushort(sh_e[k0 + 1]) << 16);
        unsigned w1 = (unsigned)__bfloat16_as_ushort(sh_e[k0 + 2]) | ((unsigned)__bfloat16_as_ushort(sh_e[k0 + 3]) << 16);
        unsigned w2 = (unsigned)__bfloat16_as_ushort(sh_e[k0 + 4]) | ((unsigned)__bfloat16_as_ushort(sh_e[k0 + 5]) << 16);
        unsigned w3 = (unsigned)__bfloat16_as_ushort(sh_e[k0 + 6]) | ((unsigned)__bfloat16_as_ushort(sh_e[k0 + 7]) << 16);
        uint4 val; val.x = w0; val.y = w1; val.z = w2; val.w = w3;
        int rb = row & 127;
        int h  = c >> 4;                 // K-half
        int c2 = c & 15;                 // chunk within half
        size_t base = ((size_t)(row >> 7) * 2 + h) * HALF_BYTES;
        unsigned off = (unsigned)rb * 256u + (unsigned)((c2 ^ (rb & 7)) << 4);
        *(uint4*)((char*)d_ebf4 + base + off) = val;
    }

    if (t == 0) {
        float sum_e = 0.f, sum_e2 = 0.f;
        #pragma unroll
        for (int w = 0; w < 8; w++) { sum_e += red1[w]; sum_e2 += red2[w]; }
        float m = sum_e * (1.0f / DIM);
        float s = sum_e2 * (1.0f / DIM);
        float V = CORRF * (s - m * m);
        d_rp[row] = make_float4(V, 16.0f * m, 1.0f / V, __int_as_float((int)lab[row]));
        atomicAdd(&d_acc.reg_sum, (double)fabsf(sum_e));
    }
}

// ---------------- persistent pair kernel ----------------
__device__ __forceinline__ void decode_tile(int li, int& bi, int& bj2) {
    int b = 0, s = 0;
    while (true) {
        int c = NB2 - (b >> 1);
        if (li < s + c) break;
        s += c; b++;
    }
    bi = b;
    bj2 = (b >> 1) + (li - s);
}

// stage buffer: A-half @ +0 (32KB), B-half rows0-255 @ +32768 (64KB)
__device__ __forceinline__ void prefetch_stage(unsigned sdst, int bi, int bj2, int h, int t) {
    const uint4* Ab = d_ebf4 + (size_t)(bi * 2 + h) * HALF_U4;
    const uint4* B0 = d_ebf4 + (size_t)(bj2 * 4 + h) * HALF_U4;
    const uint4* B1 = d_ebf4 + (size_t)(bj2 * 4 + 2 + h) * HALF_U4;
    #pragma unroll
    for (int i = 0; i < 4; i++) CP16(sdst + (t + i * NTHREADS) * 16, Ab + t + i * NTHREADS);
    #pragma unroll
    for (int i = 0; i < 4; i++) CP16(sdst + 32768 + (t + i * NTHREADS) * 16, B0 + t + i * NTHREADS);
    #pragma unroll
    for (int i = 0; i < 4; i++) CP16(sdst + 65536 + (t + i * NTHREADS) * 16, B1 + t + i * NTHREADS);
}

__global__ __launch_bounds__(NTHREADS, 1) void pair_kernel(float* __restrict__ out) {
    extern __shared__ char smem[];
    unsigned sb = smem_u32(smem);
    unsigned buf[2] = { sb, sb + STAGE_BYTES };

    int t = threadIdx.x, w = t >> 5, l = t & 31;
    int wrow = w & 3;          // M strip: 32 rows
    int wcol = w >> 2;         // N strip: 64 cols

    // per-lane ldmatrix addressing
    int rfoff = (l & 7) + (l & 8);
    int hi = l >> 4;
    int rA[2], rxA[2];
    #pragma unroll
    for (int mi = 0; mi < 2; mi++) { rA[mi] = wrow * 32 + mi * 16 + rfoff; rxA[mi] = rA[mi] & 7; }
    int rB[4], rxB[4];
    #pragma unroll
    for (int nb = 0; nb < 4; nb++) { rB[nb] = wcol * 64 + nb * 16 + rfoff; rxB[nb] = rB[nb] & 7; }

    float ps = 0.f, ns = 0.f;
    int pc = 0, nc = 0;

    int tile = blockIdx.x;
    int bi = 0, bj2 = 0;
    if (tile < NTILES2) {
        decode_tile(tile, bi, bj2);
        prefetch_stage(buf[0], bi, bj2, 0, t);
    }
    CP_COMMIT();
    int pb = 0;

    for (; tile < NTILES2; tile += GRID) {
        int ntile = tile + GRID;
        bool hasnext = ntile < NTILES2;
        int nbi = 0, nbj2 = 0;
        if (hasnext) decode_tile(ntile, nbi, nbj2);
        bool partial = (2 * bj2 <= bi);

        float acc[2][8][4];
        #pragma unroll
        for (int mi = 0; mi < 2; mi++)
            #pragma unroll
            for (int tn = 0; tn < 8; tn++)
                #pragma unroll
                for (int j = 0; j < 4; j++) acc[mi][tn][j] = 0.f;

        #pragma unroll
        for (int h = 0; h < 2; h++) {
            // prefetch next stage into the other buffer
            if (h == 0) {
                prefetch_stage(buf[pb ^ 1], bi, bj2, 1, t);
                CP_COMMIT();
                CP_WAIT(1);
            } else if (hasnext) {
                prefetch_stage(buf[pb ^ 1], nbi, nbj2, 0, t);
                CP_COMMIT();
                CP_WAIT(1);
            } else {
                CP_WAIT(0);
            }
            __syncthreads();

            unsigned aBase = buf[pb], bBase = buf[pb] + 32768;
            unsigned aRow[2], bRow[4];
            #pragma unroll
            for (int mi = 0; mi < 2; mi++) aRow[mi] = aBase + (unsigned)rA[mi] * 256u;
            #pragma unroll
            for (int nb = 0; nb < 4; nb++) bRow[nb] = bBase + (unsigned)rB[nb] * 256u;

            #pragma unroll
            for (int ks = 0; ks < 8; ks++) {
                int cc = 2 * ks + hi;
                unsigned a[2][4];
                #pragma unroll
                for (int mi = 0; mi < 2; mi++)
                    LDSM_X4(a[mi][0], a[mi][1], a[mi][2], a[mi][3],
                            aRow[mi] + (unsigned)((cc ^ rxA[mi]) << 4));
                #pragma unroll
                for (int nb = 0; nb < 4; nb++) {
                    unsigned m0, m1, m2, m3;
                    LDSM_X4(m0, m1, m2, m3, bRow[nb] + (unsigned)((cc ^ rxB[nb]) << 4));
                    #pragma unroll
                    for (int mi = 0; mi < 2; mi++) {
                        MMA_BF16(acc[mi][2 * nb],     a[mi][0], a[mi][1], a[mi][2], a[mi][3], m0, m2);
                        MMA_BF16(acc[mi][2 * nb + 1], a[mi][0], a[mi][1], a[mi][2], a[mi][3], m1, m3);
                    }
                }
            }
            __syncthreads();
            pb ^= 1;
        }

        // ---- fused epilogue (d_rp direct; next stage streams meanwhile) ----
        int jlo = (l & 3) * 2;
        float4 ipv[2][2];
        int gi00 = bi * 128 + wrow * 32 + (l >> 2);
        #pragma unroll
        for (int mi = 0; mi < 2; mi++) {
            ipv[mi][0] = d_rp[gi00 + mi * 16];
            ipv[mi][1] = d_rp[gi00 + mi * 16 + 8];
        }
        #pragma unroll
        for (int tn = 0; tn < 8; tn++) {
            int cjb = wcol * 64 + tn * 8 + jlo;
            int gj0 = bj2 * 256 + cjb;
            float4 q0 = d_rp[gj0];
            float4 q1 = d_rp[gj0 + 1];
            #pragma unroll
            for (int mi = 0; mi < 2; mi++) {
                int gi0 = gi00 + mi * 16;
                #pragma unroll
                for (int v = 0; v < 4; v++) {
                    int gi = gi0 + ((v < 2) ? 0 : 8);
                    int gj = gj0 + (v & 1);
                    if (partial && gi >= gj) continue;
                    float4 ip = ipv[mi][v >> 1];
                    float4 q = (v & 1) ? q1 : q0;
                    float dot = acc[mi][tn][v];
                    float ww  = fmaf(ip.y, q.y, -dot);
                    float num = fmaf(KCONST, ww, ip.x + q.x);
                    float dij = num * ip.z;
                    float dji = num * q.z;
                    if (__float_as_int(ip.w) == __float_as_int(q.w)) {
                        float p1 = dij - 0.01f, p2 = dji - 0.01f;
                        if (p1 > 0.f) { ps += p1; pc++; }
                        if (p2 > 0.f) { ps += p2; pc++; }
                    } else {
                        float n1 = 0.2f - dij, n2 = 0.2f - dji;
                        if (n1 > 0.f) { ns += n1; nc++; }
                        if (n2 > 0.f) { ns += n2; nc++; }
                    }
                }
            }
        }

        bi = nbi; bj2 = nbj2;
    }

    // ---- one block reduction at kernel end ----
    #pragma unroll
    for (int o = 16; o; o >>= 1) {
        ps += __shfl_xor_sync(0xffffffffu, ps, o);
        ns += __shfl_xor_sync(0xffffffffu, ns, o);
        pc += __shfl_xor_sync(0xffffffffu, pc, o);
        nc += __shfl_xor_sync(0xffffffffu, nc, o);
    }
    __shared__ float rps[16], rns[16];
    __shared__ int   rpc[16], rnc[16];
    if (l == 0) { rps[w] = ps; rns[w] = ns; rpc[w] = pc; rnc[w] = nc; }
    __syncthreads();

    if (t == 0) {
        float PS = 0.f, NS = 0.f; long long PC = 0, NC = 0;
        #pragma unroll
        for (int k = 0; k < 16; k++) { PS += rps[k]; NS += rns[k]; PC += rpc[k]; NC += rnc[k]; }
        atomicAdd(&d_acc.pos_sum, (double)PS);
        atomicAdd(&d_acc.neg_sum, (double)NS);
        atomicAdd(&d_acc.pos_cnt, (unsigned long long)PC);
        atomicAdd(&d_acc.neg_cnt, (unsigned long long)NC);

        __threadfence();
        unsigned old = atomicAdd(&d_acc.done, 1u);
        if (old == GRID - 1) {
            double psum = __ldcg(&d_acc.pos_sum);
            double nsum = __ldcg(&d_acc.neg_sum);
            double rsum = __ldcg(&d_acc.reg_sum);
            unsigned long long pcnt = __ldcg(&d_acc.pos_cnt);
            unsigned long long ncnt = __ldcg(&d_acc.neg_cnt);
            double pos = psum / ((double)pcnt + 1e-12);
            double neg = nsum / ((double)ncnt + 1e-12);
            double reg = (rsum / (double)NROW) * 0.1;
            out[0] = (float)(pos + neg + reg);
        }
    }
}

// ---------------- launch ----------------
extern "C" void kernel_launch(void* const* d_in, const int* in_sizes, int n_in,
                              void* d_out, int out_size) {
    const float*     embeds = (const float*)d_in[0];
    const long long* labels = (const long long*)d_in[1];

    void* acc_addr = nullptr;
    cudaGetSymbolAddress(&acc_addr, d_acc);

    cudaFuncSetAttribute(pair_kernel, cudaFuncAttributeMaxDynamicSharedMemorySize, 2 * STAGE_BYTES);

    cudaMemsetAsync(acc_addr, 0, sizeof(Acc));
    precompute_kernel<<<NROW, 256>>>(embeds, labels);
    pair_kernel<<<GRID, NTHREADS, 2 * STAGE_BYTES>>>((float*)d_out);
}

// round 13
// speedup vs baseline: 1.2607x; 1.2607x over previous
#include <cuda_runtime.h>
#include <cuda_bf16.h>

#define NROW 8192
#define DIM  256
#define NB   64                  // 128-row blocks
#define NTILES (NB * (NB + 1) / 2)   // 2080
#define CORRF (256.0f/255.0f)
#define KCONST (CORRF/128.0f)
#define HALF_BYTES 32768         // 128 rows x 128 bf16 (256B/row), swizzled
#define HALF_U4 (HALF_BYTES/16)  // 2048
#define NTHREADS 256
#define QT_BYTES 16384           // one operand, one K-quarter (128 rows x 128B)
#define STAGE_BYTES (2*QT_BYTES) // A-quarter + B-quarter

// ---------------- scratch ----------------
// per 128-row block b: two contiguous 32KB K-halves at (b*2+h)*32KB
__device__ uint4  d_ebf4[NB * 2 * HALF_U4];
__device__ float4 d_rp[NROW];    // {V, 16*m, 1/V, label bits}

struct Acc {
    double pos_sum, neg_sum, reg_sum;
    unsigned long long pos_cnt, neg_cnt;
    unsigned done;
};
__device__ Acc d_acc;

__device__ __forceinline__ unsigned smem_u32(const void* p) {
    unsigned a;
    asm("{ .reg .u64 t; cvta.to.shared.u64 t, %1; cvt.u32.u64 %0, t; }" : "=r"(a) : "l"(p));
    return a;
}

#define LDSM_X4(r0, r1, r2, r3, a) \
    asm volatile("ldmatrix.sync.aligned.m8n8.x4.shared.b16 {%0,%1,%2,%3}, [%4];" \
        : "=r"(r0), "=r"(r1), "=r"(r2), "=r"(r3) : "r"(a))

#define MMA_BF16(d, a0, a1, a2, a3, b0, b1) \
    asm volatile("mma.sync.aligned.m16n8k16.row.col.f32.bf16.bf16.f32 " \
        "{%0,%1,%2,%3}, {%4,%5,%6,%7}, {%8,%9}, {%0,%1,%2,%3};" \
        : "+f"((d)[0]), "+f"((d)[1]), "+f"((d)[2]), "+f"((d)[3]) \
        : "r"(a0), "r"(a1), "r"(a2), "r"(a3), "r"(b0), "r"(b1))

#define CP16(sdst, gsrc) \
    asm volatile("cp.async.cg.shared.global [%0], [%1], 16;" :: "r"(sdst), "l"(gsrc))
#define CP_COMMIT()  asm volatile("cp.async.commit_group;" ::: "memory")
#define CP_WAIT(n)   asm volatile("cp.async.wait_group %0;" :: "n"(n) : "memory")

// ---------------- precompute: normalize, stats, bf16 swizzled store ----------------
__global__ void precompute_kernel(const float* __restrict__ x,
                                  const long long* __restrict__ lab) {
    int row = blockIdx.x;
    int t = threadIdx.x;                 // feature index, blockDim = 256
    float v = x[row * DIM + t];

    float ss = v * v;
    #pragma unroll
    for (int o = 16; o; o >>= 1) ss += __shfl_xor_sync(0xffffffffu, ss, o);
    __shared__ float red[8];
    if ((t & 31) == 0) red[t >> 5] = ss;
    __syncthreads();
    float tot = red[0] + red[1] + red[2] + red[3] + red[4] + red[5] + red[6] + red[7];

    float norm = sqrtf(tot);
    float e = v / norm;

    __shared__ __nv_bfloat16 sh_e[DIM];
    sh_e[t] = __float2bfloat16(e);

    float s1 = e, s2 = e * e;
    #pragma unroll
    for (int o = 16; o; o >>= 1) {
        s1 += __shfl_xor_sync(0xffffffffu, s1, o);
        s2 += __shfl_xor_sync(0xffffffffu, s2, o);
    }
    __shared__ float red1[8], red2[8];
    if ((t & 31) == 0) { red1[t >> 5] = s1; red2[t >> 5] = s2; }
    __syncthreads();

    if (t < 32) {
        int c = t;                       // global 16B chunk index 0..31
        int k0 = c * 8;
        unsigned w0 = (unsigned)__bfloat16_as_ushort(sh_e[k0 + 0]) | ((unsigned)__bfloat16_as_ushort(sh_e[k0 + 1]) << 16);
        unsigned w1 = (unsigned)__bfloat16_as_ushort(sh_e[k0 + 2]) | ((unsigned)__bfloat16_as_ushort(sh_e[k0 + 3]) << 16);
        unsigned w2 = (unsigned)__bfloat16_as_ushort(sh_e[k0 + 4]) | ((unsigned)__bfloat16_as_ushort(sh_e[k0 + 5]) << 16);
        unsigned w3 = (unsigned)__bfloat16_as_ushort(sh_e[k0 + 6]) | ((unsigned)__bfloat16_as_ushort(sh_e[k0 + 7]) << 16);
        uint4 val; val.x = w0; val.y = w1; val.z = w2; val.w = w3;
        int rb = row & 127;
        int h  = c >> 4;                 // K-half
        int c2 = c & 15;                 // chunk within half (swizzle stays within each 8-chunk group)
        size_t base = ((size_t)(row >> 7) * 2 + h) * HALF_BYTES;
        unsigned off = (unsigned)rb * 256u + (unsigned)((c2 ^ (rb & 7)) << 4);
        *(uint4*)((char*)d_ebf4 + base + off) = val;
    }

    if (t == 0) {
        float sum_e = 0.f, sum_e2 = 0.f;
        #pragma unroll
        for (int w = 0; w < 8; w++) { sum_e += red1[w]; sum_e2 += red2[w]; }
        float m = sum_e * (1.0f / DIM);
        float s = sum_e2 * (1.0f / DIM);
        float V = CORRF * (s - m * m);
        d_rp[row] = make_float4(V, 16.0f * m, 1.0f / V, __int_as_float((int)lab[row]));
        atomicAdd(&d_acc.reg_sum, (double)fabsf(sum_e));
    }
}

// ---------------- pair kernel: 128x128 tiles, 256 threads, 2 CTAs/SM ----------------
// dyn smem: [0..2048) j-params (128 x float4), buf0 @4096 (32KB), buf1 @36864 (32KB)
#define SM_JP 0
#define SM_BUF0 4096
#define SM_TOTAL (SM_BUF0 + 2 * STAGE_BYTES)   // 69632

// copy one operand's K-quarter (16KB): 1024 uint4, 4 per thread
// block half base (uint4): (blk*2 + h) * HALF_U4 ; quarter qq selects chunks qq*8..qq*8+7 of each 16-chunk row
__device__ __forceinline__ void cp_quarter(unsigned sdst, const uint4* halfbase, int qq, int t) {
    #pragma unroll
    for (int i = 0; i < 4; i++) {
        int e = t + i * NTHREADS;          // 0..1023
        int row = e >> 3, k = e & 7;
        CP16(sdst + (unsigned)e * 16u, halfbase + row * 16 + qq * 8 + k);
    }
}

__global__ __launch_bounds__(NTHREADS, 2) void pair_kernel(float* __restrict__ out) {
    // triangular linear index -> (bi, bj), bj >= bi
    int li = blockIdx.x;
    int bi = (int)((2.0f * NB + 1.0f - sqrtf((2.0f * NB + 1.0f) * (2.0f * NB + 1.0f) - 8.0f * (float)li)) * 0.5f);
    while (NB * bi - bi * (bi - 1) / 2 > li) bi--;
    while (NB * (bi + 1) - (bi + 1) * bi / 2 <= li) bi++;
    int bj = bi + (li - (NB * bi - bi * (bi - 1) / 2));
    bool diag = (bi == bj);

    extern __shared__ char smem[];
    unsigned sb = smem_u32(smem);
    int t = threadIdx.x, w = t >> 5, l = t & 31;
    int wrow = w & 3;          // M strip: 32 rows
    int wcol = w >> 2;         // N strip: 64 cols

    const uint4* Ah[2] = { d_ebf4 + (size_t)(bi * 2) * HALF_U4,
                           d_ebf4 + (size_t)(bi * 2 + 1) * HALF_U4 };
    const uint4* Bh[2] = { d_ebf4 + (size_t)(bj * 2) * HALF_U4,
                           d_ebf4 + (size_t)(bj * 2 + 1) * HALF_U4 };

    unsigned buf[2] = { sb + SM_BUF0, sb + SM_BUF0 + STAGE_BYTES };

    // stage s (0..3): h = s>>1, qq = s&1 ; buffer layout: A @+0 (16KB), B @+16KB
    // prefetch stage 0
    cp_quarter(buf[0], Ah[0], 0, t);
    if (!diag) cp_quarter(buf[0] + QT_BYTES, Bh[0], 0, t);
    CP_COMMIT();

    if (t < 128) ((float4*)(smem + SM_JP))[t] = d_rp[bj * 128 + t];

    // per-lane ldmatrix addressing (rows are 128B = 8 chunks; swizzle confined to 8 chunks)
    int rfoff = (l & 7) + (l & 8);
    int hi = l >> 4;
    int rA[2], rxA[2];
    #pragma unroll
    for (int mi = 0; mi < 2; mi++) { rA[mi] = wrow * 32 + mi * 16 + rfoff; rxA[mi] = rA[mi] & 7; }
    int rB[4], rxB[4];
    #pragma unroll
    for (int nb = 0; nb < 4; nb++) { rB[nb] = wcol * 64 + nb * 16 + rfoff; rxB[nb] = rB[nb] & 7; }

    float acc[2][8][4];
    #pragma unroll
    for (int mi = 0; mi < 2; mi++)
        #pragma unroll
        for (int tn = 0; tn < 8; tn++)
            #pragma unroll
            for (int j = 0; j < 4; j++) acc[mi][tn][j] = 0.f;

    int pb = 0;
    #pragma unroll
    for (int s = 0; s < 4; s++) {
        if (s < 3) {
            int ns = s + 1, nh = ns >> 1, nq = ns & 1;
            cp_quarter(buf[pb ^ 1], Ah[nh], nq, t);
            if (!diag) cp_quarter(buf[pb ^ 1] + QT_BYTES, Bh[nh], nq, t);
            CP_COMMIT();
            CP_WAIT(1);
        } else {
            CP_WAIT(0);
        }
        __syncthreads();

        unsigned aBase = buf[pb];
        unsigned bBase = diag ? buf[pb] : (buf[pb] + QT_BYTES);
        unsigned aRow[2], bRow[4];
        #pragma unroll
        for (int mi = 0; mi < 2; mi++) aRow[mi] = aBase + (unsigned)rA[mi] * 128u;
        #pragma unroll
        for (int nb = 0; nb < 4; nb++) bRow[nb] = bBase + (unsigned)rB[nb] * 128u;

        #pragma unroll
        for (int ks = 0; ks < 4; ks++) {
            int cc = 2 * ks + hi;          // 0..7 chunks within the 128B row
            unsigned a[2][4];
            #pragma unroll
            for (int mi = 0; mi < 2; mi++)
                LDSM_X4(a[mi][0], a[mi][1], a[mi][2], a[mi][3],
                        aRow[mi] + (unsigned)((cc ^ rxA[mi]) << 4));
            #pragma unroll
            for (int nb = 0; nb < 4; nb++) {
                unsigned m0, m1, m2, m3;
                LDSM_X4(m0, m1, m2, m3, bRow[nb] + (unsigned)((cc ^ rxB[nb]) << 4));
                #pragma unroll
                for (int mi = 0; mi < 2; mi++) {
                    MMA_BF16(acc[mi][2 * nb],     a[mi][0], a[mi][1], a[mi][2], a[mi][3], m0, m2);
                    MMA_BF16(acc[mi][2 * nb + 1], a[mi][0], a[mi][1], a[mi][2], a[mi][3], m1, m3);
                }
            }
        }
        __syncthreads();
        pb ^= 1;
    }

    // ---- fused epilogue (j-params from smem) ----
    const float4* jp = (const float4*)(smem + SM_JP);
    int jlo = (l & 3) * 2;
    float ps = 0.f, ns = 0.f;
    int pc = 0, nc = 0;

    #pragma unroll
    for (int mi = 0; mi < 2; mi++) {
        int r0 = wrow * 32 + mi * 16 + (l >> 2);
        int gi0 = bi * 128 + r0;
        float4 ipa = d_rp[gi0];
        float4 ipb = d_rp[gi0 + 8];
        #pragma unroll
        for (int tn = 0; tn < 8; tn++) {
            #pragma unroll
            for (int v = 0; v < 4; v++) {
                int cj = wcol * 64 + tn * 8 + jlo + (v & 1);
                int ri = r0 + ((v < 2) ? 0 : 8);
                if (diag && ri >= cj) continue;
                float4 ip = (v < 2) ? ipa : ipb;
                float4 q = jp[cj];
                float dot = acc[mi][tn][v];
                float ww  = fmaf(ip.y, q.y, -dot);
                float num = fmaf(KCONST, ww, ip.x + q.x);
                float dij = num * ip.z;
                float dji = num * q.z;
                if (__float_as_int(ip.w) == __float_as_int(q.w)) {
                    float p1 = dij - 0.01f, p2 = dji - 0.01f;
                    if (p1 > 0.f) { ps += p1; pc++; }
                    if (p2 > 0.f) { ps += p2; pc++; }
                } else {
                    float n1 = 0.2f - dij, n2 = 0.2f - dji;
                    if (n1 > 0.f) { ns += n1; nc++; }
                    if (n2 > 0.f) { ns += n2; nc++; }
                }
            }
        }
    }

    // ---- block reduce ----
    #pragma unroll
    for (int o = 16; o; o >>= 1) {
        ps += __shfl_xor_sync(0xffffffffu, ps, o);
        ns += __shfl_xor_sync(0xffffffffu, ns, o);
        pc += __shfl_xor_sync(0xffffffffu, pc, o);
        nc += __shfl_xor_sync(0xffffffffu, nc, o);
    }
    __shared__ float rps[8], rns[8];
    __shared__ int   rpc[8], rnc[8];
    if (l == 0) { rps[w] = ps; rns[w] = ns; rpc[w] = pc; rnc[w] = nc; }
    __syncthreads();

    if (t == 0) {
        float PS = 0.f, NS = 0.f; long long PC = 0, NC = 0;
        #pragma unroll
        for (int k = 0; k < 8; k++) { PS += rps[k]; NS += rns[k]; PC += rpc[k]; NC += rnc[k]; }
        atomicAdd(&d_acc.pos_sum, (double)PS);
        atomicAdd(&d_acc.neg_sum, (double)NS);
        atomicAdd(&d_acc.pos_cnt, (unsigned long long)PC);
        atomicAdd(&d_acc.neg_cnt, (unsigned long long)NC);

        __threadfence();
        unsigned old = atomicAdd(&d_acc.done, 1u);
        if (old == NTILES - 1) {
            double psum = __ldcg(&d_acc.pos_sum);
            double nsum = __ldcg(&d_acc.neg_sum);
            double rsum = __ldcg(&d_acc.reg_sum);
            unsigned long long pcnt = __ldcg(&d_acc.pos_cnt);
            unsigned long long ncnt = __ldcg(&d_acc.neg_cnt);
            double pos = psum / ((double)pcnt + 1e-12);
            double neg = nsum / ((double)ncnt + 1e-12);
            double reg = (rsum / (double)NROW) * 0.1;
            out[0] = (float)(pos + neg + reg);
        }
    }
}

// ---------------- launch ----------------
extern "C" void kernel_launch(void* const* d_in, const int* in_sizes, int n_in,
                              void* d_out, int out_size) {
    const float*     embeds = (const float*)d_in[0];
    const long long* labels = (const long long*)d_in[1];

    void* acc_addr = nullptr;
    cudaGetSymbolAddress(&acc_addr, d_acc);

    cudaFuncSetAttribute(pair_kernel, cudaFuncAttributeMaxDynamicSharedMemorySize, SM_TOTAL);

    cudaMemsetAsync(acc_addr, 0, sizeof(Acc));
    precompute_kernel<<<NROW, 256>>>(embeds, labels);
    pair_kernel<<<NTILES, NTHREADS, SM_TOTAL>>>((float*)d_out);
}

// round 14
// speedup vs baseline: 1.3667x; 1.0840x over previous
#include <cuda_runtime.h>
#include <cuda_bf16.h>

#define NROW 8192
#define DIM  256
#define NB   64                  // 128-row blocks
#define NTILES (NB * (NB + 1) / 2)   // 2080
#define CORRF (256.0f/255.0f)
#define KCONST (CORRF/128.0f)
#define HALF_BYTES 32768         // 128 rows x 128 bf16 (256B/row), swizzled
#define HALF_U4 (HALF_BYTES/16)  // 2048
#define NTHREADS 256
#define QT_BYTES 16384           // one operand, one K-quarter (128 rows x 128B)
#define STAGE_BYTES (2*QT_BYTES) // A-quarter + B-quarter

// ---------------- scratch ----------------
__device__ uint4  d_ebf4[NB * 2 * HALF_U4];
__device__ float4 d_rp[NROW];    // {V, 16*m, 1/V, label bits}

struct Acc {
    double pos_sum, neg_sum, reg_sum;
    unsigned long long pos_cnt, neg_cnt;
    unsigned done;
};
__device__ Acc d_acc;

__device__ __forceinline__ unsigned smem_u32(const void* p) {
    unsigned a;
    asm("{ .reg .u64 t; cvta.to.shared.u64 t, %1; cvt.u32.u64 %0, t; }" : "=r"(a) : "l"(p));
    return a;
}

#define LDSM_X4(r0, r1, r2, r3, a) \
    asm volatile("ldmatrix.sync.aligned.m8n8.x4.shared.b16 {%0,%1,%2,%3}, [%4];" \
        : "=r"(r0), "=r"(r1), "=r"(r2), "=r"(r3) : "r"(a))

#define MMA_BF16(d, a0, a1, a2, a3, b0, b1) \
    asm volatile("mma.sync.aligned.m16n8k16.row.col.f32.bf16.bf16.f32 " \
        "{%0,%1,%2,%3}, {%4,%5,%6,%7}, {%8,%9}, {%0,%1,%2,%3};" \
        : "+f"((d)[0]), "+f"((d)[1]), "+f"((d)[2]), "+f"((d)[3]) \
        : "r"(a0), "r"(a1), "r"(a2), "r"(a3), "r"(b0), "r"(b1))

#define CP16(sdst, gsrc) \
    asm volatile("cp.async.cg.shared.global [%0], [%1], 16;" :: "r"(sdst), "l"(gsrc))
#define CP_COMMIT()  asm volatile("cp.async.commit_group;" ::: "memory")
#define CP_WAIT(n)   asm volatile("cp.async.wait_group %0;" :: "n"(n) : "memory")

// ---------------- precompute: normalize, stats, bf16 swizzled store ----------------
__global__ void precompute_kernel(const float* __restrict__ x,
                                  const long long* __restrict__ lab) {
    int row = blockIdx.x;
    int t = threadIdx.x;                 // feature index, blockDim = 256
    float v = x[row * DIM + t];

    float ss = v * v;
    #pragma unroll
    for (int o = 16; o; o >>= 1) ss += __shfl_xor_sync(0xffffffffu, ss, o);
    __shared__ float red[8];
    if ((t & 31) == 0) red[t >> 5] = ss;
    __syncthreads();
    float tot = red[0] + red[1] + red[2] + red[3] + red[4] + red[5] + red[6] + red[7];

    float norm = sqrtf(tot);
    float e = v / norm;

    __shared__ __nv_bfloat16 sh_e[DIM];
    sh_e[t] = __float2bfloat16(e);

    float s1 = e, s2 = e * e;
    #pragma unroll
    for (int o = 16; o; o >>= 1) {
        s1 += __shfl_xor_sync(0xffffffffu, s1, o);
        s2 += __shfl_xor_sync(0xffffffffu, s2, o);
    }
    __shared__ float red1[8], red2[8];
    if ((t & 31) == 0) { red1[t >> 5] = s1; red2[t >> 5] = s2; }
    __syncthreads();

    if (t < 32) {
        int c = t;                       // global 16B chunk index 0..31
        int k0 = c * 8;
        unsigned w0 = (unsigned)__bfloat16_as_ushort(sh_e[k0 + 0]) | ((unsigned)__bfloat16_as_ushort(sh_e[k0 + 1]) << 16);
        unsigned w1 = (unsigned)__bfloat16_as_ushort(sh_e[k0 + 2]) | ((unsigned)__bfloat16_as_ushort(sh_e[k0 + 3]) << 16);
        unsigned w2 = (unsigned)__bfloat16_as_ushort(sh_e[k0 + 4]) | ((unsigned)__bfloat16_as_ushort(sh_e[k0 + 5]) << 16);
        unsigned w3 = (unsigned)__bfloat16_as_ushort(sh_e[k0 + 6]) | ((unsigned)__bfloat16_as_ushort(sh_e[k0 + 7]) << 16);
        uint4 val; val.x = w0; val.y = w1; val.z = w2; val.w = w3;
        int rb = row & 127;
        int h  = c >> 4;                 // K-half
        int c2 = c & 15;                 // chunk within half
        size_t base = ((size_t)(row >> 7) * 2 + h) * HALF_BYTES;
        unsigned off = (unsigned)rb * 256u + (unsigned)((c2 ^ (rb & 7)) << 4);
        *(uint4*)((char*)d_ebf4 + base + off) = val;
    }

    if (t == 0) {
        float sum_e = 0.f, sum_e2 = 0.f;
        #pragma unroll
        for (int w = 0; w < 8; w++) { sum_e += red1[w]; sum_e2 += red2[w]; }
        float m = sum_e * (1.0f / DIM);
        float s = sum_e2 * (1.0f / DIM);
        float V = CORRF * (s - m * m);
        d_rp[row] = make_float4(V, 16.0f * m, 1.0f / V, __int_as_float((int)lab[row]));
        atomicAdd(&d_acc.reg_sum, (double)fabsf(sum_e));
    }
}

// ---------------- pair kernel: 128x128 tiles, 256 threads, 2 CTAs/SM, 3-stage ring ----------------
// dyn smem: [0..2048) j-params (128 x float4), 3 stage buffers of 32KB @4096
#define SM_JP 0
#define SM_BUF0 4096
#define SM_TOTAL (SM_BUF0 + 3 * STAGE_BYTES)   // 102400

__device__ __forceinline__ void cp_quarter(unsigned sdst, const uint4* halfbase, int qq, int t) {
    #pragma unroll
    for (int i = 0; i < 4; i++) {
        int e = t + i * NTHREADS;          // 0..1023
        int row = e >> 3, k = e & 7;
        CP16(sdst + (unsigned)e * 16u, halfbase + row * 16 + qq * 8 + k);
    }
}

__global__ __launch_bounds__(NTHREADS, 2) void pair_kernel(float* __restrict__ out) {
    // triangular linear index -> (bi, bj), bj >= bi
    int li = blockIdx.x;
    int bi = (int)((2.0f * NB + 1.0f - sqrtf((2.0f * NB + 1.0f) * (2.0f * NB + 1.0f) - 8.0f * (float)li)) * 0.5f);
    while (NB * bi - bi * (bi - 1) / 2 > li) bi--;
    while (NB * (bi + 1) - (bi + 1) * bi / 2 <= li) bi++;
    int bj = bi + (li - (NB * bi - bi * (bi - 1) / 2));
    bool diag = (bi == bj);

    extern __shared__ char smem[];
    unsigned sb = smem_u32(smem);
    int t = threadIdx.x, w = t >> 5, l = t & 31;
    int wrow = w & 3;          // M strip: 32 rows
    int wcol = w >> 2;         // N strip: 64 cols

    const uint4* Ah[2] = { d_ebf4 + (size_t)(bi * 2) * HALF_U4,
                           d_ebf4 + (size_t)(bi * 2 + 1) * HALF_U4 };
    const uint4* Bh[2] = { d_ebf4 + (size_t)(bj * 2) * HALF_U4,
                           d_ebf4 + (size_t)(bj * 2 + 1) * HALF_U4 };

    unsigned buf[3] = { sb + SM_BUF0, sb + SM_BUF0 + STAGE_BYTES, sb + SM_BUF0 + 2 * STAGE_BYTES };

    // stages s=0..3: h = s>>1, qq = s&1 ; buffer s%3: A @+0, B @+16KB
    cp_quarter(buf[0], Ah[0], 0, t);
    if (!diag) cp_quarter(buf[0] + QT_BYTES, Bh[0], 0, t);
    CP_COMMIT();
    cp_quarter(buf[1], Ah[0], 1, t);
    if (!diag) cp_quarter(buf[1] + QT_BYTES, Bh[0], 1, t);
    CP_COMMIT();

    if (t < 128) ((float4*)(smem + SM_JP))[t] = d_rp[bj * 128 + t];

    // per-lane ldmatrix addressing
    int rfoff = (l & 7) + (l & 8);
    int hi = l >> 4;
    int rA[2], rxA[2];
    #pragma unroll
    for (int mi = 0; mi < 2; mi++) { rA[mi] = wrow * 32 + mi * 16 + rfoff; rxA[mi] = rA[mi] & 7; }
    int rB[4], rxB[4];
    #pragma unroll
    for (int nb = 0; nb < 4; nb++) { rB[nb] = wcol * 64 + nb * 16 + rfoff; rxB[nb] = rB[nb] & 7; }

    float acc[2][8][4];
    #pragma unroll
    for (int mi = 0; mi < 2; mi++)
        #pragma unroll
        for (int tn = 0; tn < 8; tn++)
            #pragma unroll
            for (int j = 0; j < 4; j++) acc[mi][tn][j] = 0.f;

    #pragma unroll
    for (int s = 0; s < 4; s++) {
        if (s < 3) CP_WAIT(1); else CP_WAIT(0);
        __syncthreads();
        // prefetch stage s+2 into buf[(s+2)%3] (freed by MMA of stage s-1, guarded by the sync above)
        if (s < 2) {
            int ns = s + 2, nh = ns >> 1, nq = ns & 1;
            unsigned nb_ = buf[ns % 3];
            cp_quarter(nb_, Ah[nh], nq, t);
            if (!diag) cp_quarter(nb_ + QT_BYTES, Bh[nh], nq, t);
            CP_COMMIT();
        }

        unsigned aBase = buf[s % 3];
        unsigned bBase = diag ? aBase : (aBase + QT_BYTES);
        unsigned aRow[2], bRow[4];
        #pragma unroll
        for (int mi = 0; mi < 2; mi++) aRow[mi] = aBase + (unsigned)rA[mi] * 128u;
        #pragma unroll
        for (int nb = 0; nb < 4; nb++) bRow[nb] = bBase + (unsigned)rB[nb] * 128u;

        #pragma unroll
        for (int ks = 0; ks < 4; ks++) {
            int cc = 2 * ks + hi;          // chunk 0..7 within the 128B row
            unsigned a[2][4];
            #pragma unroll
            for (int mi = 0; mi < 2; mi++)
                LDSM_X4(a[mi][0], a[mi][1], a[mi][2], a[mi][3],
                        aRow[mi] + (unsigned)((cc ^ rxA[mi]) << 4));
            #pragma unroll
            for (int nb = 0; nb < 4; nb++) {
                unsigned m0, m1, m2, m3;
                LDSM_X4(m0, m1, m2, m3, bRow[nb] + (unsigned)((cc ^ rxB[nb]) << 4));
                #pragma unroll
                for (int mi = 0; mi < 2; mi++) {
                    MMA_BF16(acc[mi][2 * nb],     a[mi][0], a[mi][1], a[mi][2], a[mi][3], m0, m2);
                    MMA_BF16(acc[mi][2 * nb + 1], a[mi][0], a[mi][1], a[mi][2], a[mi][3], m1, m3);
                }
            }
        }
    }
    __syncthreads();   // all MMA consumers done before epilogue reuses nothing; orders jp reads too

    // ---- fused epilogue (hoisted q0/q1; diag-specialized) ----
    const float4* jp = (const float4*)(smem + SM_JP);
    int jlo = (l & 3) * 2;
    float ps = 0.f, ns = 0.f;
    int pc = 0, nc = 0;

    int r00 = wrow * 32 + (l >> 2);
    float4 ipv[2][2];
    #pragma unroll
    for (int mi = 0; mi < 2; mi++) {
        ipv[mi][0] = d_rp[bi * 128 + r00 + mi * 16];
        ipv[mi][1] = d_rp[bi * 128 + r00 + mi * 16 + 8];
    }

    #pragma unroll
    for (int tn = 0; tn < 8; tn++) {
        int cjb = wcol * 64 + tn * 8 + jlo;
        float4 q0 = jp[cjb];
        float4 q1 = jp[cjb + 1];
        #pragma unroll
        for (int mi = 0; mi < 2; mi++) {
            int r0 = r00 + mi * 16;
            #pragma unroll
            for (int v = 0; v < 4; v++) {
                if (diag) {
                    int ri = r0 + ((v < 2) ? 0 : 8);
                    int cj = cjb + (v & 1);
                    if (ri >= cj) continue;
                }
                float4 ip = ipv[mi][v >> 1];
                float4 q = (v & 1) ? q1 : q0;
                float dot = acc[mi][tn][v];
                float ww  = fmaf(ip.y, q.y, -dot);
                float num = fmaf(KCONST, ww, ip.x + q.x);
                float dij = num * ip.z;
                float dji = num * q.z;
                if (__float_as_int(ip.w) == __float_as_int(q.w)) {
                    float p1 = dij - 0.01f, p2 = dji - 0.01f;
                    if (p1 > 0.f) { ps += p1; pc++; }
                    if (p2 > 0.f) { ps += p2; pc++; }
                } else {
                    float n1 = 0.2f - dij, n2 = 0.2f - dji;
                    if (n1 > 0.f) { ns += n1; nc++; }
                    if (n2 > 0.f) { ns += n2; nc++; }
                }
            }
        }
    }

    // ---- block reduce ----
    #pragma unroll
    for (int o = 16; o; o >>= 1) {
        ps += __shfl_xor_sync(0xffffffffu, ps, o);
        ns += __shfl_xor_sync(0xffffffffu, ns, o);
        pc += __shfl_xor_sync(0xffffffffu, pc, o);
        nc += __shfl_xor_sync(0xffffffffu, nc, o);
    }
    __shared__ float rps[8], rns[8];
    __shared__ int   rpc[8], rnc[8];
    if (l == 0) { rps[w] = ps; rns[w] = ns; rpc[w] = pc; rnc[w] = nc; }
    __syncthreads();

    if (t == 0) {
        float PS = 0.f, NS = 0.f; long long PC = 0, NC = 0;
        #pragma unroll
        for (int k = 0; k < 8; k++) { PS += rps[k]; NS += rns[k]; PC += rpc[k]; NC += rnc[k]; }
        atomicAdd(&d_acc.pos_sum, (double)PS);
        atomicAdd(&d_acc.neg_sum, (double)NS);
        atomicAdd(&d_acc.pos_cnt, (unsigned long long)PC);
        atomicAdd(&d_acc.neg_cnt, (unsigned long long)NC);

        __threadfence();
        unsigned old = atomicAdd(&d_acc.done, 1u);
        if (old == NTILES - 1) {
            double psum = __ldcg(&d_acc.pos_sum);
            double nsum = __ldcg(&d_acc.neg_sum);
            double rsum = __ldcg(&d_acc.reg_sum);
            unsigned long long pcnt = __ldcg(&d_acc.pos_cnt);
            unsigned long long ncnt = __ldcg(&d_acc.neg_cnt);
            double pos = psum / ((double)pcnt + 1e-12);
            double neg = nsum / ((double)ncnt + 1e-12);
            double reg = (rsum / (double)NROW) * 0.1;
            out[0] = (float)(pos + neg + reg);
        }
    }
}

// ---------------- launch ----------------
extern "C" void kernel_launch(void* const* d_in, const int* in_sizes, int n_in,
                              void* d_out, int out_size) {
    const float*     embeds = (const float*)d_in[0];
    const long long* labels = (const long long*)d_in[1];

    void* acc_addr = nullptr;
    cudaGetSymbolAddress(&acc_addr, d_acc);

    cudaFuncSetAttribute(pair_kernel, cudaFuncAttributeMaxDynamicSharedMemorySize, SM_TOTAL);

    cudaMemsetAsync(acc_addr, 0, sizeof(Acc));
    precompute_kernel<<<NROW, 256>>>(embeds, labels);
    pair_kernel<<<NTILES, NTHREADS, SM_TOTAL>>>((float*)d_out);
}

// round 15
// speedup vs baseline: 1.5452x; 1.1307x over previous
#include <cuda_runtime.h>
#include <cuda_bf16.h>

#define NROW 8192
#define DIM  256
#define NB   64                  // 128-row blocks
#define NTILES (NB * (NB + 1) / 2)   // 2080
#define CORRF (256.0f/255.0f)
#define KCONST (CORRF/128.0f)
#define HALF_BYTES 32768         // 128 rows x 128 bf16 (256B/row), swizzled
#define HALF_U4 (HALF_BYTES/16)  // 2048
#define NTHREADS 256
#define QT_BYTES 16384           // one operand, one K-quarter (128 rows x 128B)
#define STAGE_BYTES (2*QT_BYTES) // A-quarter + B-quarter

// ---------------- scratch ----------------
__device__ uint4  d_ebf4[NB * 2 * HALF_U4];
__device__ float4 d_rp[NROW];    // {V, 16*m, 1/V, label bits}

struct Acc {
    double pos_sum, neg_sum, reg_sum;
    unsigned long long pos_cnt, neg_cnt;
    unsigned done;
};
__device__ Acc d_acc;

__device__ __forceinline__ unsigned smem_u32(const void* p) {
    unsigned a;
    asm("{ .reg .u64 t; cvta.to.shared.u64 t, %1; cvt.u32.u64 %0, t; }" : "=r"(a) : "l"(p));
    return a;
}

#define LDSM_X4(r0, r1, r2, r3, a) \
    asm volatile("ldmatrix.sync.aligned.m8n8.x4.shared.b16 {%0,%1,%2,%3}, [%4];" \
        : "=r"(r0), "=r"(r1), "=r"(r2), "=r"(r3) : "r"(a))

#define MMA_BF16(d, a0, a1, a2, a3, b0, b1) \
    asm volatile("mma.sync.aligned.m16n8k16.row.col.f32.bf16.bf16.f32 " \
        "{%0,%1,%2,%3}, {%4,%5,%6,%7}, {%8,%9}, {%0,%1,%2,%3};" \
        : "+f"((d)[0]), "+f"((d)[1]), "+f"((d)[2]), "+f"((d)[3]) \
        : "r"(a0), "r"(a1), "r"(a2), "r"(a3), "r"(b0), "r"(b1))

#define CP16(sdst, gsrc) \
    asm volatile("cp.async.cg.shared.global [%0], [%1], 16;" :: "r"(sdst), "l"(gsrc))
#define CP_COMMIT()  asm volatile("cp.async.commit_group;" ::: "memory")
#define CP_WAIT(n)   asm volatile("cp.async.wait_group %0;" :: "n"(n) : "memory")

// ---------------- precompute: one warp per row ----------------
__global__ void precompute_kernel(const float* __restrict__ x,
                                  const long long* __restrict__ lab) {
    int w = threadIdx.x >> 5, l = threadIdx.x & 31;
    int row = blockIdx.x * 8 + w;

    const float4* xr = (const float4*)(x + (size_t)row * DIM) + l * 2;
    float4 a = xr[0], b = xr[1];
    float v[8] = { a.x, a.y, a.z, a.w, b.x, b.y, b.z, b.w };

    float ss = 0.f;
    #pragma unroll
    for (int i = 0; i < 8; i++) ss = fmaf(v[i], v[i], ss);
    #pragma unroll
    for (int o = 16; o; o >>= 1) ss += __shfl_xor_sync(0xffffffffu, ss, o);

    float r = rsqrtf(ss);
    float e[8];
    float s1 = 0.f, s2 = 0.f;
    #pragma unroll
    for (int i = 0; i < 8; i++) {
        e[i] = v[i] * r;
        s1 += e[i];
        s2 = fmaf(e[i], e[i], s2);
    }
    #pragma unroll
    for (int o = 16; o; o >>= 1) {
        s1 += __shfl_xor_sync(0xffffffffu, s1, o);
        s2 += __shfl_xor_sync(0xffffffffu, s2, o);
    }

    // pack this lane's 8 bf16 and store swizzled (chunk c = l)
    unsigned pw[4];
    #pragma unroll
    for (int i = 0; i < 4; i++) {
        unsigned lo = (unsigned)__bfloat16_as_ushort(__float2bfloat16(e[2 * i]));
        unsigned hi = (unsigned)__bfloat16_as_ushort(__float2bfloat16(e[2 * i + 1]));
        pw[i] = lo | (hi << 16);
    }
    uint4 val; val.x = pw[0]; val.y = pw[1]; val.z = pw[2]; val.w = pw[3];
    int rb = row & 127;
    int h  = l >> 4;
    int c2 = l & 15;
    size_t base = ((size_t)(row >> 7) * 2 + h) * HALF_BYTES;
    unsigned off = (unsigned)rb * 256u + (unsigned)((c2 ^ (rb & 7)) << 4);
    *(uint4*)((char*)d_ebf4 + base + off) = val;

    __shared__ float wabs[8];
    if (l == 0) {
        float m = s1 * (1.0f / DIM);
        float s = s2 * (1.0f / DIM);
        float V = CORRF * (s - m * m);
        d_rp[row] = make_float4(V, 16.0f * m, 1.0f / V, __int_as_float((int)lab[row]));
        wabs[w] = fabsf(s1);
    }
    __syncthreads();
    if (threadIdx.x == 0) {
        float t = 0.f;
        #pragma unroll
        for (int k = 0; k < 8; k++) t += wabs[k];
        atomicAdd(&d_acc.reg_sum, (double)t);
    }
}

// ---------------- pair kernel: 128x128 tiles, 256 threads, 2 CTAs/SM, 3-stage ring ----------------
#define SM_JP 0
#define SM_BUF0 4096
#define SM_TOTAL (SM_BUF0 + 3 * STAGE_BYTES)   // 102400

__device__ __forceinline__ void cp_quarter(unsigned sdst, const uint4* halfbase, int qq, int t) {
    #pragma unroll
    for (int i = 0; i < 4; i++) {
        int e = t + i * NTHREADS;          // 0..1023
        int row = e >> 3, k = e & 7;
        CP16(sdst + (unsigned)e * 16u, halfbase + row * 16 + qq * 8 + k);
    }
}

__global__ __launch_bounds__(NTHREADS, 2) void pair_kernel(float* __restrict__ out) {
    // triangular linear index -> (bi, bj), bj >= bi
    int li = blockIdx.x;
    int bi = (int)((2.0f * NB + 1.0f - sqrtf((2.0f * NB + 1.0f) * (2.0f * NB + 1.0f) - 8.0f * (float)li)) * 0.5f);
    while (NB * bi - bi * (bi - 1) / 2 > li) bi--;
    while (NB * (bi + 1) - (bi + 1) * bi / 2 <= li) bi++;
    int bj = bi + (li - (NB * bi - bi * (bi - 1) / 2));
    bool diag = (bi == bj);

    extern __shared__ char smem[];
    unsigned sb = smem_u32(smem);
    int t = threadIdx.x, w = t >> 5, l = t & 31;
    int wrow = w & 3;          // M strip: 32 rows
    int wcol = w >> 2;         // N strip: 64 cols

    const uint4* Ah[2] = { d_ebf4 + (size_t)(bi * 2) * HALF_U4,
                           d_ebf4 + (size_t)(bi * 2 + 1) * HALF_U4 };
    const uint4* Bh[2] = { d_ebf4 + (size_t)(bj * 2) * HALF_U4,
                           d_ebf4 + (size_t)(bj * 2 + 1) * HALF_U4 };

    unsigned buf[3] = { sb + SM_BUF0, sb + SM_BUF0 + STAGE_BYTES, sb + SM_BUF0 + 2 * STAGE_BYTES };

    cp_quarter(buf[0], Ah[0], 0, t);
    if (!diag) cp_quarter(buf[0] + QT_BYTES, Bh[0], 0, t);
    CP_COMMIT();
    cp_quarter(buf[1], Ah[0], 1, t);
    if (!diag) cp_quarter(buf[1] + QT_BYTES, Bh[0], 1, t);
    CP_COMMIT();

    if (t < 128) ((float4*)(smem + SM_JP))[t] = d_rp[bj * 128 + t];

    // per-lane ldmatrix addressing
    int rfoff = (l & 7) + (l & 8);
    int hi = l >> 4;
    int rA[2], rxA[2];
    #pragma unroll
    for (int mi = 0; mi < 2; mi++) { rA[mi] = wrow * 32 + mi * 16 + rfoff; rxA[mi] = rA[mi] & 7; }
    int rB[4], rxB[4];
    #pragma unroll
    for (int nb = 0; nb < 4; nb++) { rB[nb] = wcol * 64 + nb * 16 + rfoff; rxB[nb] = rB[nb] & 7; }

    float acc[2][8][4];
    #pragma unroll
    for (int mi = 0; mi < 2; mi++)
        #pragma unroll
        for (int tn = 0; tn < 8; tn++)
            #pragma unroll
            for (int j = 0; j < 4; j++) acc[mi][tn][j] = 0.f;

    #pragma unroll
    for (int s = 0; s < 4; s++) {
        if (s < 3) CP_WAIT(1); else CP_WAIT(0);
        __syncthreads();
        if (s < 2) {
            int ns = s + 2, nh = ns >> 1, nq = ns & 1;
            unsigned nb_ = buf[ns % 3];
            cp_quarter(nb_, Ah[nh], nq, t);
            if (!diag) cp_quarter(nb_ + QT_BYTES, Bh[nh], nq, t);
            CP_COMMIT();
        }

        unsigned aBase = buf[s % 3];
        unsigned bBase = diag ? aBase : (aBase + QT_BYTES);
        unsigned aRow[2], bRow[4];
        #pragma unroll
        for (int mi = 0; mi < 2; mi++) aRow[mi] = aBase + (unsigned)rA[mi] * 128u;
        #pragma unroll
        for (int nb = 0; nb < 4; nb++) bRow[nb] = bBase + (unsigned)rB[nb] * 128u;

        #pragma unroll
        for (int ks = 0; ks < 4; ks++) {
            int cc = 2 * ks + hi;
            unsigned a[2][4];
            #pragma unroll
            for (int mi = 0; mi < 2; mi++)
                LDSM_X4(a[mi][0], a[mi][1], a[mi][2], a[mi][3],
                        aRow[mi] + (unsigned)((cc ^ rxA[mi]) << 4));
            #pragma unroll
            for (int nb = 0; nb < 4; nb++) {
                unsigned m0, m1, m2, m3;
                LDSM_X4(m0, m1, m2, m3, bRow[nb] + (unsigned)((cc ^ rxB[nb]) << 4));
                #pragma unroll
                for (int mi = 0; mi < 2; mi++) {
                    MMA_BF16(acc[mi][2 * nb],     a[mi][0], a[mi][1], a[mi][2], a[mi][3], m0, m2);
                    MMA_BF16(acc[mi][2 * nb + 1], a[mi][0], a[mi][1], a[mi][2], a[mi][3], m1, m3);
                }
            }
        }
    }
    __syncthreads();

    // ---- fused epilogue (threshold form) ----
    const float4* jp = (const float4*)(smem + SM_JP);
    int jlo = (l & 3) * 2;
    float ps = 0.f, ns = 0.f;
    int pc = 0, nc = 0;

    int r00 = wrow * 32 + (l >> 2);
    float4 ipv[2][2];
    float Ui[2][2];
    #pragma unroll
    for (int mi = 0; mi < 2; mi++) {
        ipv[mi][0] = d_rp[bi * 128 + r00 + mi * 16];
        ipv[mi][1] = d_rp[bi * 128 + r00 + mi * 16 + 8];
        Ui[mi][0] = 0.2f * ipv[mi][0].x;
        Ui[mi][1] = 0.2f * ipv[mi][1].x;
    }

    #pragma unroll
    for (int tn = 0; tn < 8; tn++) {
        int cjb = wcol * 64 + tn * 8 + jlo;
        float4 q0 = jp[cjb];
        float4 q1 = jp[cjb + 1];
        float U0 = 0.2f * q0.x;
        float U1 = 0.2f * q1.x;
        #pragma unroll
        for (int mi = 0; mi < 2; mi++) {
            int r0 = r00 + mi * 16;
            #pragma unroll
            for (int v = 0; v < 4; v++) {
                if (diag) {
                    int ri = r0 + ((v < 2) ? 0 : 8);
                    int cj = cjb + (v & 1);
                    if (ri >= cj) continue;
                }
                float4 ip = ipv[mi][v >> 1];
                float4 q = (v & 1) ? q1 : q0;
                float Uqi = Ui[mi][v >> 1];
                float Uqj = (v & 1) ? U1 : U0;
                float dot = acc[mi][tn][v];
                float ww  = fmaf(ip.y, q.y, -dot);
                float num = fmaf(KCONST, ww, ip.x + q.x);
                if (__float_as_int(ip.w) == __float_as_int(q.w)) {
                    // pos: d > 0.01  <=>  num > 0.01*V ;  contrib = num*iv - 0.01
                    if (num > 0.05f * Uqi) { ps += fmaf(num, ip.z, -0.01f); pc++; }
                    if (num > 0.05f * Uqj) { ps += fmaf(num, q.z, -0.01f); pc++; }
                } else {
                    // neg: d < 0.2   <=>  num < 0.2*V  ;  contrib = 0.2 - num*iv
                    if (num < Uqi) { ns += fmaf(num, -ip.z, 0.2f); nc++; }
                    if (num < Uqj) { ns += fmaf(num, -q.z, 0.2f); nc++; }
                }
            }
        }
    }

    // ---- block reduce ----
    #pragma unroll
    for (int o = 16; o; o >>= 1) {
        ps += __shfl_xor_sync(0xffffffffu, ps, o);
        ns += __shfl_xor_sync(0xffffffffu, ns, o);
        pc += __shfl_xor_sync(0xffffffffu, pc, o);
        nc += __shfl_xor_sync(0xffffffffu, nc, o);
    }
    __shared__ float rps[8], rns[8];
    __shared__ int   rpc[8], rnc[8];
    if (l == 0) { rps[w] = ps; rns[w] = ns; rpc[w] = pc; rnc[w] = nc; }
    __syncthreads();

    if (t == 0) {
        float PS = 0.f, NS = 0.f; long long PC = 0, NC = 0;
        #pragma unroll
        for (int k = 0; k < 8; k++) { PS += rps[k]; NS += rns[k]; PC += rpc[k]; NC += rnc[k]; }
        atomicAdd(&d_acc.pos_sum, (double)PS);
        atomicAdd(&d_acc.neg_sum, (double)NS);
        atomicAdd(&d_acc.pos_cnt, (unsigned long long)PC);
        atomicAdd(&d_acc.neg_cnt, (unsigned long long)NC);

        __threadfence();
        unsigned old = atomicAdd(&d_acc.done, 1u);
        if (old == NTILES - 1) {
            double psum = __ldcg(&d_acc.pos_sum);
            double nsum = __ldcg(&d_acc.neg_sum);
            double rsum = __ldcg(&d_acc.reg_sum);
            unsigned long long pcnt = __ldcg(&d_acc.pos_cnt);
            unsigned long long ncnt = __ldcg(&d_acc.neg_cnt);
            double pos = psum / ((double)pcnt + 1e-12);
            double neg = nsum / ((double)ncnt + 1e-12);
            double reg = (rsum / (double)NROW) * 0.1;
            out[0] = (float)(pos + neg + reg);
        }
    }
}

// ---------------- launch ----------------
extern "C" void kernel_launch(void* const* d_in, const int* in_sizes, int n_in,
                              void* d_out, int out_size) {
    const float*     embeds = (const float*)d_in[0];
    const long long* labels = (const long long*)d_in[1];

    void* acc_addr = nullptr;
    cudaGetSymbolAddress(&acc_addr, d_acc);

    cudaFuncSetAttribute(pair_kernel, cudaFuncAttributeMaxDynamicSharedMemorySize, SM_TOTAL);

    cudaMemsetAsync(acc_addr, 0, sizeof(Acc));
    precompute_kernel<<<NROW / 8, 256>>>(embeds, labels);
    pair_kernel<<<NTILES, NTHREADS, SM_TOTAL>>>((float*)d_out);
}